// round 3
// baseline (speedup 1.0000x reference)
#include <cuda_runtime.h>
#include <math.h>

#define D_DIM 1024
#define F_DIM 512
#define N_OUTG 8
#define E_TOT 16
#define T_MAX 1024

#define BM 64
#define BN 64
#define BK 32
#define AS 40   // words per row: 4 groups * 10 (8 data + stride-5 pairing)

// -------- scratch (no allocation allowed) --------
__device__ int   g_sel_ids[T_MAX * 3];
__device__ float g_sel_w[T_MAX * 3];
__device__ int   g_cnt[E_TOT];
__device__ int   g_list[E_TOT * T_MAX];          // packed (t<<2)|k
__device__ float g_H [T_MAX * 3 * F_DIM];        // h = silu(g)*u per pair
__device__ float g_Ys[T_MAX * 3 * D_DIM];        // weighted down-proj per pair

// ---------------- tf32 helpers ----------------
__device__ __forceinline__ unsigned f2tf(float f) {
    unsigned u;
    asm("cvt.rna.tf32.f32 %0, %1;" : "=r"(u) : "f"(f));
    return u;
}
__device__ __forceinline__ void mma_tf32(float* c, const unsigned* a,
                                         unsigned b0, unsigned b1) {
    asm volatile(
        "mma.sync.aligned.m16n8k8.row.col.f32.tf32.tf32.f32 "
        "{%0,%1,%2,%3}, {%4,%5,%6,%7}, {%8,%9}, {%0,%1,%2,%3};\n"
        : "+f"(c[0]), "+f"(c[1]), "+f"(c[2]), "+f"(c[3])
        : "r"(a[0]), "r"(a[1]), "r"(a[2]), "r"(a[3]), "r"(b0), "r"(b1));
}
// store one (row, 8k-group) unit: pairs {lo[e], hi[e]} -> conflict-free STS.64
__device__ __forceinline__ void st_unit(unsigned* S, int r, int grp,
                                        float4 lo, float4 hi) {
    unsigned* p = S + r * AS + grp * 10;
    *(uint2*)(p + 0) = make_uint2(f2tf(lo.x), f2tf(hi.x));
    *(uint2*)(p + 2) = make_uint2(f2tf(lo.y), f2tf(hi.y));
    *(uint2*)(p + 4) = make_uint2(f2tf(lo.z), f2tf(hi.z));
    *(uint2*)(p + 6) = make_uint2(f2tf(lo.w), f2tf(hi.w));
}

// ======================= router (exact fp32) =======================
__global__ void router_kernel(const float* __restrict__ x,
                              const float* __restrict__ w_out,
                              const float* __restrict__ w_in,
                              float* __restrict__ selw_out, int write_selw)
{
    int t = blockIdx.x;
    const float* xr = x + (size_t)t * D_DIM;
    int warp = threadIdx.x >> 5, lane = threadIdx.x & 31;
    __shared__ float s_dots[24];

    #pragma unroll
    for (int j = 0; j < 3; ++j) {
        int dix = warp * 3 + j;
        const float* wr = (dix < N_OUTG) ? (w_out + (size_t)dix * D_DIM)
                                         : (w_in  + (size_t)(dix - N_OUTG) * D_DIM);
        float acc = 0.f;
        for (int k = lane * 4; k < D_DIM; k += 128) {
            float4 a = *(const float4*)(xr + k);
            float4 b = *(const float4*)(wr + k);
            acc += a.x * b.x + a.y * b.y + a.z * b.z + a.w * b.w;
        }
        #pragma unroll
        for (int off = 16; off > 0; off >>= 1)
            acc += __shfl_xor_sync(0xffffffffu, acc, off);
        if (lane == 0) s_dots[dix] = acc;
    }
    __syncthreads();

    if (threadIdx.x == 0) {
        float l[N_OUTG];
        #pragma unroll
        for (int i = 0; i < N_OUTG; ++i) l[i] = s_dots[i];
        int a1 = 0;
        #pragma unroll
        for (int i = 1; i < N_OUTG; ++i) if (l[i] > l[a1]) a1 = i;
        int a2 = (a1 == 0) ? 1 : 0;
        #pragma unroll
        for (int i = 0; i < N_OUTG; ++i) if (i != a1 && l[i] > l[a2]) a2 = i;
        float e2 = expf(l[a2] - l[a1]);
        float w0 = 1.f / (1.f + e2);
        float w1 = e2 / (1.f + e2);

        float sA0 = s_dots[8 + a1 * 2], sA1 = s_dots[8 + a1 * 2 + 1];
        int i0 = (sA1 > sA0) ? 1 : 0;
        float sB0 = s_dots[8 + a2 * 2], sB1 = s_dots[8 + a2 * 2 + 1];
        int i2 = (sB1 > sB0) ? 1 : 0;

        int   ids[3] = { a1 * 2 + i0, a1 * 2 + (1 - i0), a2 * 2 + i2 };
        float ws [3] = { w0, w0, w1 };
        #pragma unroll
        for (int k = 0; k < 3; ++k) {
            g_sel_ids[t * 3 + k] = ids[k];
            g_sel_w  [t * 3 + k] = ws[k];
            if (write_selw) selw_out[t * 3 + k] = ws[k];
        }
    }
}

// ======================= grouping =======================
__global__ void zero_cnt_kernel() {
    if (threadIdx.x < E_TOT) g_cnt[threadIdx.x] = 0;
}
__global__ void group_kernel(int T) {
    int p = blockIdx.x * blockDim.x + threadIdx.x;
    if (p < 3 * T) {
        int t = p / 3, k = p - 3 * t;
        int e = g_sel_ids[p];
        int pos = atomicAdd(&g_cnt[e], 1);
        g_list[e * T_MAX + pos] = (t << 2) | k;
    }
}

// ======================= gate+up GEMM (tf32 MMA, fused SwiGLU) =======================
__global__ __launch_bounds__(128)
void gateup_kernel(const float* __restrict__ x,
                   const float* __restrict__ wg,
                   const float* __restrict__ wu)
{
    int e  = blockIdx.y;
    int n  = g_cnt[e];
    int t0 = blockIdx.z * BM;
    if (t0 >= n) return;
    int f0 = blockIdx.x * BN;

    __shared__ unsigned As[BM * AS];
    __shared__ unsigned Gs[BN * AS];
    __shared__ unsigned Us[BN * AS];
    __shared__ int s_pr[BM];

    int tid  = threadIdx.x;
    int warp = tid >> 5, lane = tid & 31;
    int wm = warp >> 1, wn = warp & 1;
    int g  = lane >> 2, t4 = lane & 3;

    if (tid < BM) {
        int rowt = t0 + tid;
        s_pr[tid] = (rowt < n) ? g_list[e * T_MAX + rowt] : -1;
    }
    __syncthreads();

    // global load mapping: units (row = (tid>>2) + 32j, group = tid&3)
    int lr  = tid >> 2;            // 0..31
    int grp = tid & 3;             // 0..3
    const float* ap[2]; const float* gp[2]; const float* up[2];
    #pragma unroll
    for (int j = 0; j < 2; ++j) {
        int r = lr + 32 * j;
        int pr = s_pr[r];
        ap[j] = x + (size_t)((pr < 0) ? 0 : (pr >> 2)) * D_DIM + grp * 8;
        gp[j] = wg + ((size_t)e * F_DIM + f0 + r) * D_DIM + grp * 8;
        up[j] = wu + ((size_t)e * F_DIM + f0 + r) * D_DIM + grp * 8;
    }

    float4 pa[2][2], pg[2][2], pu[2][2];
    #pragma unroll
    for (int j = 0; j < 2; ++j) {
        pa[j][0] = *(const float4*)(ap[j]);     pa[j][1] = *(const float4*)(ap[j] + 4);
        pg[j][0] = *(const float4*)(gp[j]);     pg[j][1] = *(const float4*)(gp[j] + 4);
        pu[j][0] = *(const float4*)(up[j]);     pu[j][1] = *(const float4*)(up[j] + 4);
    }

    float accG[2][4][4] = {}, accU[2][4][4] = {};

    for (int k0 = 0; k0 < D_DIM; k0 += BK) {
        #pragma unroll
        for (int j = 0; j < 2; ++j) {
            int r = lr + 32 * j;
            st_unit(As, r, grp, pa[j][0], pa[j][1]);
            st_unit(Gs, r, grp, pg[j][0], pg[j][1]);
            st_unit(Us, r, grp, pu[j][0], pu[j][1]);
        }
        __syncthreads();

        int kn = k0 + BK;
        if (kn < D_DIM) {
            #pragma unroll
            for (int j = 0; j < 2; ++j) {
                pa[j][0] = *(const float4*)(ap[j] + kn);  pa[j][1] = *(const float4*)(ap[j] + kn + 4);
                pg[j][0] = *(const float4*)(gp[j] + kn);  pg[j][1] = *(const float4*)(gp[j] + kn + 4);
                pu[j][0] = *(const float4*)(up[j] + kn);  pu[j][1] = *(const float4*)(up[j] + kn + 4);
            }
        }

        #pragma unroll
        for (int ks = 0; ks < 4; ++ks) {
            unsigned a[2][4];
            #pragma unroll
            for (int mf = 0; mf < 2; ++mf) {
                int mb = wm * 32 + mf * 16;
                uint2 p0 = *(const uint2*)(As + (mb + g    ) * AS + ks * 10 + t4 * 2);
                uint2 p1 = *(const uint2*)(As + (mb + g + 8) * AS + ks * 10 + t4 * 2);
                a[mf][0] = p0.x; a[mf][1] = p1.x; a[mf][2] = p0.y; a[mf][3] = p1.y;
            }
            #pragma unroll
            for (int nf = 0; nf < 4; ++nf) {
                int nb = wn * 32 + nf * 8;
                uint2 bg = *(const uint2*)(Gs + (nb + g) * AS + ks * 10 + t4 * 2);
                mma_tf32(accG[0][nf], a[0], bg.x, bg.y);
                mma_tf32(accG[1][nf], a[1], bg.x, bg.y);
                uint2 bu = *(const uint2*)(Us + (nb + g) * AS + ks * 10 + t4 * 2);
                mma_tf32(accU[0][nf], a[0], bu.x, bu.y);
                mma_tf32(accU[1][nf], a[1], bu.x, bu.y);
            }
        }
        __syncthreads();
    }

    // epilogue: h = silu(g)*u scattered to pair rows
    #pragma unroll
    for (int mf = 0; mf < 2; ++mf) {
        #pragma unroll
        for (int h = 0; h < 2; ++h) {
            int m = wm * 32 + mf * 16 + g + h * 8;
            int rowt = t0 + m;
            if (rowt < n) {
                int pr = s_pr[m];
                int prow = (pr >> 2) * 3 + (pr & 3);
                float* Hrow = g_H + (size_t)prow * F_DIM + f0;
                #pragma unroll
                for (int nf = 0; nf < 4; ++nf) {
                    float gv0 = accG[mf][nf][h * 2], gv1 = accG[mf][nf][h * 2 + 1];
                    float uv0 = accU[mf][nf][h * 2], uv1 = accU[mf][nf][h * 2 + 1];
                    float h0 = gv0 / (1.f + expf(-gv0)) * uv0;
                    float h1 = gv1 / (1.f + expf(-gv1)) * uv1;
                    *(float2*)(Hrow + wn * 32 + nf * 8 + t4 * 2) = make_float2(h0, h1);
                }
            }
        }
    }
}

// ======================= down GEMM (tf32 MMA, weighted) =======================
__global__ __launch_bounds__(128)
void down_kernel(const float* __restrict__ wd)
{
    int e  = blockIdx.y;
    int n  = g_cnt[e];
    int t0 = blockIdx.z * BM;
    if (t0 >= n) return;
    int d0 = blockIdx.x * BN;

    __shared__ unsigned Hs[BM * AS];
    __shared__ unsigned Ws[BN * AS];
    __shared__ int s_pr[BM];

    int tid  = threadIdx.x;
    int warp = tid >> 5, lane = tid & 31;
    int wm = warp >> 1, wn = warp & 1;
    int g  = lane >> 2, t4 = lane & 3;

    if (tid < BM) {
        int rowt = t0 + tid;
        s_pr[tid] = (rowt < n) ? g_list[e * T_MAX + rowt] : -1;
    }
    __syncthreads();

    int lr  = tid >> 2;
    int grp = tid & 3;
    const float* hp[2]; const float* wp[2];
    #pragma unroll
    for (int j = 0; j < 2; ++j) {
        int r = lr + 32 * j;
        int pr = s_pr[r];
        int prow = (pr < 0) ? 0 : ((pr >> 2) * 3 + (pr & 3));
        hp[j] = g_H + (size_t)prow * F_DIM + grp * 8;
        wp[j] = wd + ((size_t)e * D_DIM + d0 + r) * F_DIM + grp * 8;
    }

    float4 ph[2][2], pw[2][2];
    #pragma unroll
    for (int j = 0; j < 2; ++j) {
        ph[j][0] = *(const float4*)(hp[j]);  ph[j][1] = *(const float4*)(hp[j] + 4);
        pw[j][0] = *(const float4*)(wp[j]);  pw[j][1] = *(const float4*)(wp[j] + 4);
    }

    float acc[2][4][4] = {};

    for (int k0 = 0; k0 < F_DIM; k0 += BK) {
        #pragma unroll
        for (int j = 0; j < 2; ++j) {
            int r = lr + 32 * j;
            st_unit(Hs, r, grp, ph[j][0], ph[j][1]);
            st_unit(Ws, r, grp, pw[j][0], pw[j][1]);
        }
        __syncthreads();

        int kn = k0 + BK;
        if (kn < F_DIM) {
            #pragma unroll
            for (int j = 0; j < 2; ++j) {
                ph[j][0] = *(const float4*)(hp[j] + kn);  ph[j][1] = *(const float4*)(hp[j] + kn + 4);
                pw[j][0] = *(const float4*)(wp[j] + kn);  pw[j][1] = *(const float4*)(wp[j] + kn + 4);
            }
        }

        #pragma unroll
        for (int ks = 0; ks < 4; ++ks) {
            unsigned a[2][4];
            #pragma unroll
            for (int mf = 0; mf < 2; ++mf) {
                int mb = wm * 32 + mf * 16;
                uint2 p0 = *(const uint2*)(Hs + (mb + g    ) * AS + ks * 10 + t4 * 2);
                uint2 p1 = *(const uint2*)(Hs + (mb + g + 8) * AS + ks * 10 + t4 * 2);
                a[mf][0] = p0.x; a[mf][1] = p1.x; a[mf][2] = p0.y; a[mf][3] = p1.y;
            }
            #pragma unroll
            for (int nf = 0; nf < 4; ++nf) {
                int nb = wn * 32 + nf * 8;
                uint2 bw = *(const uint2*)(Ws + (nb + g) * AS + ks * 10 + t4 * 2);
                mma_tf32(acc[0][nf], a[0], bw.x, bw.y);
                mma_tf32(acc[1][nf], a[1], bw.x, bw.y);
            }
        }
        __syncthreads();
    }

    #pragma unroll
    for (int mf = 0; mf < 2; ++mf) {
        #pragma unroll
        for (int h = 0; h < 2; ++h) {
            int m = wm * 32 + mf * 16 + g + h * 8;
            int rowt = t0 + m;
            if (rowt < n) {
                int pr = s_pr[m];
                int prow = (pr >> 2) * 3 + (pr & 3);
                float wsel = g_sel_w[prow];
                float* Yrow = g_Ys + (size_t)prow * D_DIM + d0;
                #pragma unroll
                for (int nf = 0; nf < 4; ++nf) {
                    float y0 = acc[mf][nf][h * 2] * wsel;
                    float y1 = acc[mf][nf][h * 2 + 1] * wsel;
                    *(float2*)(Yrow + wn * 32 + nf * 8 + t4 * 2) = make_float2(y0, y1);
                }
            }
        }
    }
}

// ======================= deterministic combine =======================
__global__ void combine_kernel(float* __restrict__ out, int T)
{
    int gid = blockIdx.x * blockDim.x + threadIdx.x;
    int total = T * (D_DIM / 4);
    if (gid < total) {
        int t  = gid / (D_DIM / 4);
        int dq = gid - t * (D_DIM / 4);
        const float4* y0 = (const float4*)(g_Ys + (size_t)(t * 3 + 0) * D_DIM) + dq;
        const float4* y1 = (const float4*)(g_Ys + (size_t)(t * 3 + 1) * D_DIM) + dq;
        const float4* y2 = (const float4*)(g_Ys + (size_t)(t * 3 + 2) * D_DIM) + dq;
        float4 a = *y0, b = *y1, c = *y2;
        ((float4*)out)[gid] = make_float4(a.x + b.x + c.x, a.y + b.y + c.y,
                                          a.z + b.z + c.z, a.w + b.w + c.w);
    }
}

// ======================= launch =======================
extern "C" void kernel_launch(void* const* d_in, const int* in_sizes, int n_in,
                              void* d_out, int out_size)
{
    const float* x     = (const float*)d_in[0];
    const float* w_out = (const float*)d_in[1];
    const float* w_in  = (const float*)d_in[2];
    const float* wg    = (const float*)d_in[3];
    const float* wu    = (const float*)d_in[4];
    const float* wd    = (const float*)d_in[5];
    float* out = (float*)d_out;

    int T = in_sizes[0] / D_DIM;
    if (T > T_MAX) T = T_MAX;
    int write_selw = (out_size >= T * D_DIM + 3 * T) ? 1 : 0;

    router_kernel<<<T, 256>>>(x, w_out, w_in, out + (size_t)T * D_DIM, write_selw);
    zero_cnt_kernel<<<1, 32>>>();
    group_kernel<<<(3 * T + 255) / 256, 256>>>(T);

    int ttiles = (T + BM - 1) / BM;
    dim3 g1(F_DIM / BN, E_TOT, ttiles);
    gateup_kernel<<<g1, 128>>>(x, wg, wu);
    dim3 g2(D_DIM / BN, E_TOT, ttiles);
    down_kernel<<<g2, 128>>>(wd);

    combine_kernel<<<(T * (D_DIM / 4) + 255) / 256, 256>>>(out, T);
}

// round 4
// speedup vs baseline: 1.0981x; 1.0981x over previous
#include <cuda_runtime.h>
#include <math.h>

#define D_DIM 1024
#define F_DIM 512
#define N_OUTG 8
#define E_TOT 16
#define T_MAX 1024
#define BM 64
#define BN 64
#define BK 32

// -------- scratch (no allocation allowed) --------
__device__ int   g_cnt[E_TOT];
__device__ int   g_list[E_TOT * T_MAX];          // packed (t<<2)|k
__device__ float g_sel_w[T_MAX * 3];
__device__ float g_H [T_MAX * 3 * F_DIM];        // h = silu(g)*u per pair
__device__ float g_Ys[T_MAX * 3 * D_DIM];        // weighted down-proj per pair

// ---------------- tf32 helpers ----------------
__device__ __forceinline__ unsigned f2tf(float f) {
    unsigned u;
    asm("cvt.rna.tf32.f32 %0, %1;" : "=r"(u) : "f"(f));
    return u;
}
__device__ __forceinline__ void mma_tf32(float* c, const unsigned* a,
                                         unsigned b0, unsigned b1) {
    asm volatile(
        "mma.sync.aligned.m16n8k8.row.col.f32.tf32.tf32.f32 "
        "{%0,%1,%2,%3}, {%4,%5,%6,%7}, {%8,%9}, {%0,%1,%2,%3};\n"
        : "+f"(c[0]), "+f"(c[1]), "+f"(c[2]), "+f"(c[3])
        : "r"(a[0]), "r"(a[1]), "r"(a[2]), "r"(a[3]), "r"(b0), "r"(b1));
}
// A-operand block store: rows (g, g+8) of a 16x8 block, 4 k-values each.
// block = 128 words, slot l = 4 words (the LDS.128 fragment of lane l), XOR-kb swizzled.
__device__ __forceinline__ void stA(unsigned* blk, int kb, int g, int khi,
                                    float4 va, float4 vb) {
    unsigned* q = blk + 2 * khi;
    *(uint2*)(q + (((g*4+0)^kb) << 2)) = make_uint2(f2tf(va.x), f2tf(vb.x));
    *(uint2*)(q + (((g*4+1)^kb) << 2)) = make_uint2(f2tf(va.y), f2tf(vb.y));
    *(uint2*)(q + (((g*4+2)^kb) << 2)) = make_uint2(f2tf(va.z), f2tf(vb.z));
    *(uint2*)(q + (((g*4+3)^kb) << 2)) = make_uint2(f2tf(va.w), f2tf(vb.w));
}
// B-operand block store: row n (=g within 8-block), 8 k-values (lo=k0..3, hi=k4..7).
// block = 64 words, slot l = 2 words (LDS.64 fragment of lane l), XOR-kb swizzled.
__device__ __forceinline__ void stB(unsigned* blk, int kb, int g,
                                    float4 lo, float4 hi) {
    *(uint2*)(blk + (((g*4+0)^kb) << 1)) = make_uint2(f2tf(lo.x), f2tf(hi.x));
    *(uint2*)(blk + (((g*4+1)^kb) << 1)) = make_uint2(f2tf(lo.y), f2tf(hi.y));
    *(uint2*)(blk + (((g*4+2)^kb) << 1)) = make_uint2(f2tf(lo.z), f2tf(hi.z));
    *(uint2*)(blk + (((g*4+3)^kb) << 1)) = make_uint2(f2tf(lo.w), f2tf(hi.w));
}

// ======================= router (exact fp32, fused grouping) =======================
__global__ void router_kernel(const float* __restrict__ x,
                              const float* __restrict__ w_out,
                              const float* __restrict__ w_in,
                              float* __restrict__ selw_out, int write_selw)
{
    int t = blockIdx.x;
    const float* xr = x + (size_t)t * D_DIM;
    int warp = threadIdx.x >> 5, lane = threadIdx.x & 31;
    __shared__ float s_dots[24];

    #pragma unroll
    for (int j = 0; j < 3; ++j) {
        int dix = warp * 3 + j;
        const float* wr = (dix < N_OUTG) ? (w_out + (size_t)dix * D_DIM)
                                         : (w_in  + (size_t)(dix - N_OUTG) * D_DIM);
        float acc = 0.f;
        for (int k = lane * 4; k < D_DIM; k += 128) {
            float4 a = *(const float4*)(xr + k);
            float4 b = *(const float4*)(wr + k);
            acc += a.x * b.x + a.y * b.y + a.z * b.z + a.w * b.w;
        }
        #pragma unroll
        for (int off = 16; off > 0; off >>= 1)
            acc += __shfl_xor_sync(0xffffffffu, acc, off);
        if (lane == 0) s_dots[dix] = acc;
    }
    __syncthreads();

    if (threadIdx.x == 0) {
        float l[N_OUTG];
        #pragma unroll
        for (int i = 0; i < N_OUTG; ++i) l[i] = s_dots[i];
        int a1 = 0;
        #pragma unroll
        for (int i = 1; i < N_OUTG; ++i) if (l[i] > l[a1]) a1 = i;
        int a2 = (a1 == 0) ? 1 : 0;
        #pragma unroll
        for (int i = 0; i < N_OUTG; ++i) if (i != a1 && l[i] > l[a2]) a2 = i;
        float e2 = expf(l[a2] - l[a1]);
        float w0 = 1.f / (1.f + e2);
        float w1 = e2 / (1.f + e2);

        float sA0 = s_dots[8 + a1 * 2], sA1 = s_dots[8 + a1 * 2 + 1];
        int i0 = (sA1 > sA0) ? 1 : 0;
        float sB0 = s_dots[8 + a2 * 2], sB1 = s_dots[8 + a2 * 2 + 1];
        int i2 = (sB1 > sB0) ? 1 : 0;

        int   ids[3] = { a1 * 2 + i0, a1 * 2 + (1 - i0), a2 * 2 + i2 };
        float ws [3] = { w0, w0, w1 };
        #pragma unroll
        for (int k = 0; k < 3; ++k) {
            g_sel_w[t * 3 + k] = ws[k];
            if (write_selw) selw_out[t * 3 + k] = ws[k];
            int e = ids[k];
            int pos = atomicAdd(&g_cnt[e], 1);
            g_list[e * T_MAX + pos] = (t << 2) | k;
        }
    }
}

// ======================= gate+up GEMM (tf32 MMA, frag-packed, DB) =======================
__global__ __launch_bounds__(128)
void gateup_kernel(const float* __restrict__ x,
                   const float* __restrict__ wg,
                   const float* __restrict__ wu)
{
    int e  = blockIdx.y;
    int n  = g_cnt[e];
    int t0 = blockIdx.z * BM;
    if (t0 >= n) return;
    int f0 = blockIdx.x * BN;

    __shared__ unsigned As[2][2048];
    __shared__ unsigned Gs[2][2048];
    __shared__ unsigned Us[2][2048];

    int tid  = threadIdx.x;
    int warp = tid >> 5, lane = tid & 31;
    int wm = warp >> 1, wn = warp & 1;
    int g  = lane >> 2, t4 = lane & 3;

    // ---- producer mappings ----
    // A units: (mb = mbA + 2j, gA, kb, khi), rows gA & gA+8 of 16-row block
    int gA = (tid >> 3) & 7, kq = tid & 7;
    int kbA = kq >> 1, khiA = kq & 1, mbA = tid >> 6;
    int koffA = kbA * 8 + khiA * 4;
    const float* axp[2][2];
    #pragma unroll
    for (int j = 0; j < 2; ++j)
        #pragma unroll
        for (int rr = 0; rr < 2; ++rr) {
            int r = (mbA + 2 * j) * 16 + gA + rr * 8;
            int rowt = t0 + r;
            int pr = (rowt < n) ? g_list[e * T_MAX + rowt] : -1;
            axp[j][rr] = x + (size_t)((pr < 0) ? 0 : (pr >> 2)) * D_DIM + koffA;
        }
    // B units: (n = nB0 + 32j, kbB), 8 consecutive k
    int nB0 = tid >> 2, kbB = tid & 3;
    const float* gxp[2]; const float* uxp[2];
    #pragma unroll
    for (int j = 0; j < 2; ++j) {
        int r = nB0 + 32 * j;
        gxp[j] = wg + ((size_t)e * F_DIM + f0 + r) * D_DIM + kbB * 8;
        uxp[j] = wu + ((size_t)e * F_DIM + f0 + r) * D_DIM + kbB * 8;
    }

    float4 pa[2][2], pg[2][2], pu[2][2];
    #pragma unroll
    for (int j = 0; j < 2; ++j) {
        pa[j][0] = *(const float4*)(axp[j][0]);
        pa[j][1] = *(const float4*)(axp[j][1]);
        pg[j][0] = *(const float4*)(gxp[j]);
        pg[j][1] = *(const float4*)(gxp[j] + 4);
        pu[j][0] = *(const float4*)(uxp[j]);
        pu[j][1] = *(const float4*)(uxp[j] + 4);
    }

    float accG[2][4][4] = {}, accU[2][4][4] = {};

    const int NT = D_DIM / BK;
    for (int kt = 0; kt < NT; ++kt) {
        int buf = kt & 1;
        unsigned* Ab = As[buf];
        unsigned* Gb = Gs[buf];
        unsigned* Ub = Us[buf];
        #pragma unroll
        for (int j = 0; j < 2; ++j) {
            stA(Ab + (((mbA + 2 * j) * 4 + kbA) << 7), kbA, gA, khiA,
                pa[j][0], pa[j][1]);
            int nn = nB0 + 32 * j;
            stB(Gb + ((((nn >> 3) * 4 + kbB)) << 6), kbB, nn & 7, pg[j][0], pg[j][1]);
            stB(Ub + ((((nn >> 3) * 4 + kbB)) << 6), kbB, nn & 7, pu[j][0], pu[j][1]);
        }
        __syncthreads();

        if (kt + 1 < NT) {
            int kn = (kt + 1) * BK;
            #pragma unroll
            for (int j = 0; j < 2; ++j) {
                pa[j][0] = *(const float4*)(axp[j][0] + kn);
                pa[j][1] = *(const float4*)(axp[j][1] + kn);
                pg[j][0] = *(const float4*)(gxp[j] + kn);
                pg[j][1] = *(const float4*)(gxp[j] + kn + 4);
                pu[j][0] = *(const float4*)(uxp[j] + kn);
                pu[j][1] = *(const float4*)(uxp[j] + kn + 4);
            }
        }

        #pragma unroll
        for (int ks = 0; ks < 4; ++ks) {
            unsigned a[2][4];
            #pragma unroll
            for (int mf = 0; mf < 2; ++mf) {
                uint4 v = *(const uint4*)(Ab + (((wm * 2 + mf) * 4 + ks) << 7)
                                             + ((lane ^ ks) << 2));
                a[mf][0] = v.x; a[mf][1] = v.y; a[mf][2] = v.z; a[mf][3] = v.w;
            }
            #pragma unroll
            for (int nf = 0; nf < 4; ++nf) {
                int boff = (((wn * 4 + nf) * 4 + ks) << 6) + ((lane ^ ks) << 1);
                uint2 bg = *(const uint2*)(Gb + boff);
                mma_tf32(accG[0][nf], a[0], bg.x, bg.y);
                mma_tf32(accG[1][nf], a[1], bg.x, bg.y);
                uint2 bu = *(const uint2*)(Ub + boff);
                mma_tf32(accU[0][nf], a[0], bu.x, bu.y);
                mma_tf32(accU[1][nf], a[1], bu.x, bu.y);
            }
        }
    }

    // epilogue: h = silu(g)*u scattered to pair rows
    #pragma unroll
    for (int mf = 0; mf < 2; ++mf) {
        #pragma unroll
        for (int h = 0; h < 2; ++h) {
            int m = wm * 32 + mf * 16 + g + h * 8;
            int rowt = t0 + m;
            if (rowt < n) {
                int pr = g_list[e * T_MAX + rowt];
                int prow = (pr >> 2) * 3 + (pr & 3);
                float* Hrow = g_H + (size_t)prow * F_DIM + f0;
                #pragma unroll
                for (int nf = 0; nf < 4; ++nf) {
                    float gv0 = accG[mf][nf][h * 2], gv1 = accG[mf][nf][h * 2 + 1];
                    float uv0 = accU[mf][nf][h * 2], uv1 = accU[mf][nf][h * 2 + 1];
                    float h0 = gv0 / (1.f + expf(-gv0)) * uv0;
                    float h1 = gv1 / (1.f + expf(-gv1)) * uv1;
                    *(float2*)(Hrow + wn * 32 + nf * 8 + t4 * 2) = make_float2(h0, h1);
                }
            }
        }
    }
}

// ======================= down GEMM (tf32 MMA, frag-packed, DB, weighted) =======================
__global__ __launch_bounds__(128)
void down_kernel(const float* __restrict__ wd)
{
    int e  = blockIdx.y;
    int n  = g_cnt[e];
    int t0 = blockIdx.z * BM;
    if (t0 >= n) return;
    int d0 = blockIdx.x * BN;

    __shared__ unsigned Hs[2][2048];
    __shared__ unsigned Ws[2][2048];

    int tid  = threadIdx.x;
    int warp = tid >> 5, lane = tid & 31;
    int wm = warp >> 1, wn = warp & 1;
    int g  = lane >> 2, t4 = lane & 3;

    int gA = (tid >> 3) & 7, kq = tid & 7;
    int kbA = kq >> 1, khiA = kq & 1, mbA = tid >> 6;
    int koffA = kbA * 8 + khiA * 4;
    const float* hxp[2][2];
    #pragma unroll
    for (int j = 0; j < 2; ++j)
        #pragma unroll
        for (int rr = 0; rr < 2; ++rr) {
            int r = (mbA + 2 * j) * 16 + gA + rr * 8;
            int rowt = t0 + r;
            int pr = (rowt < n) ? g_list[e * T_MAX + rowt] : -1;
            int prow = (pr < 0) ? 0 : ((pr >> 2) * 3 + (pr & 3));
            hxp[j][rr] = g_H + (size_t)prow * F_DIM + koffA;
        }
    int nB0 = tid >> 2, kbB = tid & 3;
    const float* wxp[2];
    #pragma unroll
    for (int j = 0; j < 2; ++j) {
        int r = nB0 + 32 * j;
        wxp[j] = wd + ((size_t)e * D_DIM + d0 + r) * F_DIM + kbB * 8;
    }

    float4 ph[2][2], pw[2][2];
    #pragma unroll
    for (int j = 0; j < 2; ++j) {
        ph[j][0] = *(const float4*)(hxp[j][0]);
        ph[j][1] = *(const float4*)(hxp[j][1]);
        pw[j][0] = *(const float4*)(wxp[j]);
        pw[j][1] = *(const float4*)(wxp[j] + 4);
    }

    float acc[2][4][4] = {};

    const int NT = F_DIM / BK;
    for (int kt = 0; kt < NT; ++kt) {
        int buf = kt & 1;
        unsigned* Ab = Hs[buf];
        unsigned* Bb = Ws[buf];
        #pragma unroll
        for (int j = 0; j < 2; ++j) {
            stA(Ab + (((mbA + 2 * j) * 4 + kbA) << 7), kbA, gA, khiA,
                ph[j][0], ph[j][1]);
            int nn = nB0 + 32 * j;
            stB(Bb + ((((nn >> 3) * 4 + kbB)) << 6), kbB, nn & 7, pw[j][0], pw[j][1]);
        }
        __syncthreads();

        if (kt + 1 < NT) {
            int kn = (kt + 1) * BK;
            #pragma unroll
            for (int j = 0; j < 2; ++j) {
                ph[j][0] = *(const float4*)(hxp[j][0] + kn);
                ph[j][1] = *(const float4*)(hxp[j][1] + kn);
                pw[j][0] = *(const float4*)(wxp[j] + kn);
                pw[j][1] = *(const float4*)(wxp[j] + kn + 4);
            }
        }

        #pragma unroll
        for (int ks = 0; ks < 4; ++ks) {
            unsigned a[2][4];
            #pragma unroll
            for (int mf = 0; mf < 2; ++mf) {
                uint4 v = *(const uint4*)(Ab + (((wm * 2 + mf) * 4 + ks) << 7)
                                             + ((lane ^ ks) << 2));
                a[mf][0] = v.x; a[mf][1] = v.y; a[mf][2] = v.z; a[mf][3] = v.w;
            }
            #pragma unroll
            for (int nf = 0; nf < 4; ++nf) {
                int boff = (((wn * 4 + nf) * 4 + ks) << 6) + ((lane ^ ks) << 1);
                uint2 bw = *(const uint2*)(Bb + boff);
                mma_tf32(acc[0][nf], a[0], bw.x, bw.y);
                mma_tf32(acc[1][nf], a[1], bw.x, bw.y);
            }
        }
    }

    #pragma unroll
    for (int mf = 0; mf < 2; ++mf) {
        #pragma unroll
        for (int h = 0; h < 2; ++h) {
            int m = wm * 32 + mf * 16 + g + h * 8;
            int rowt = t0 + m;
            if (rowt < n) {
                int pr = g_list[e * T_MAX + rowt];
                int prow = (pr >> 2) * 3 + (pr & 3);
                float wsel = g_sel_w[prow];
                float* Yrow = g_Ys + (size_t)prow * D_DIM + d0;
                #pragma unroll
                for (int nf = 0; nf < 4; ++nf) {
                    float y0 = acc[mf][nf][h * 2] * wsel;
                    float y1 = acc[mf][nf][h * 2 + 1] * wsel;
                    *(float2*)(Yrow + wn * 32 + nf * 8 + t4 * 2) = make_float2(y0, y1);
                }
            }
        }
    }
}

// ======================= deterministic combine (+ counter reset) =======================
__global__ void combine_kernel(float* __restrict__ out, int T)
{
    if (blockIdx.x == 0 && threadIdx.x < E_TOT) g_cnt[threadIdx.x] = 0;
    int gid = blockIdx.x * blockDim.x + threadIdx.x;
    int total = T * (D_DIM / 4);
    if (gid < total) {
        int t  = gid / (D_DIM / 4);
        int dq = gid - t * (D_DIM / 4);
        const float4* y0 = (const float4*)(g_Ys + (size_t)(t * 3 + 0) * D_DIM) + dq;
        const float4* y1 = (const float4*)(g_Ys + (size_t)(t * 3 + 1) * D_DIM) + dq;
        const float4* y2 = (const float4*)(g_Ys + (size_t)(t * 3 + 2) * D_DIM) + dq;
        float4 a = *y0, b = *y1, c = *y2;
        ((float4*)out)[gid] = make_float4(a.x + b.x + c.x, a.y + b.y + c.y,
                                          a.z + b.z + c.z, a.w + b.w + c.w);
    }
}

// ======================= launch =======================
extern "C" void kernel_launch(void* const* d_in, const int* in_sizes, int n_in,
                              void* d_out, int out_size)
{
    const float* x     = (const float*)d_in[0];
    const float* w_out = (const float*)d_in[1];
    const float* w_in  = (const float*)d_in[2];
    const float* wg    = (const float*)d_in[3];
    const float* wu    = (const float*)d_in[4];
    const float* wd    = (const float*)d_in[5];
    float* out = (float*)d_out;

    int T = in_sizes[0] / D_DIM;
    if (T > T_MAX) T = T_MAX;
    int write_selw = (out_size >= T * D_DIM + 3 * T) ? 1 : 0;

    router_kernel<<<T, 256>>>(x, w_out, w_in, out + (size_t)T * D_DIM, write_selw);

    int ttiles = (T + BM - 1) / BM;
    dim3 g1(F_DIM / BN, E_TOT, ttiles);
    gateup_kernel<<<g1, 128>>>(x, wg, wu);
    dim3 g2(D_DIM / BN, E_TOT, ttiles);
    down_kernel<<<g2, 128>>>(wd);

    combine_kernel<<<(T * (D_DIM / 4) + 255) / 256, 256>>>(out, T);
}